// round 1
// baseline (speedup 1.0000x reference)
#include <cuda_runtime.h>

// Problem: B=4, T=4096, WINDOW=1024, MAX_DISP=2.0
// out[b,t] = sum_k relu(1 - |s - k|) * x[k],  s = w[b]*coeff[t] + t
// Tent kernel => linear interpolation of x at s, with out-of-range k dropped.

#define T_DIM 4096
#define B_DIM 4

__global__ void tvp_kernel(const float* __restrict__ w,
                           const float* __restrict__ x,
                           float* __restrict__ out) {
    int idx = blockIdx.x * blockDim.x + threadIdx.x;  // 0 .. B*T-1
    if (idx >= B_DIM * T_DIM) return;

    int b = idx >> 12;          // idx / 4096
    int t = idx & (T_DIM - 1);  // idx % 4096

    // coeff[t] = 2.0 * ((t % 1024)/1024 - 0.5)
    float wn = (float)(t & 1023);
    float c = 2.0f * (wn * (1.0f / 1024.0f) - 0.5f);

    float wb = w[b];
    float s = wb * c + (float)t;   // match reference mul-then-add

    float k0f = floorf(s);
    int   k0  = (int)k0f;
    float frac = s - k0f;          // in [0,1)

    float acc = 0.0f;
    if (k0 >= 0 && k0 < T_DIM)
        acc += (1.0f - frac) * x[k0];
    int k1 = k0 + 1;
    if (k1 >= 0 && k1 < T_DIM)
        acc += frac * x[k1];

    out[idx] = acc;
}

extern "C" void kernel_launch(void* const* d_in, const int* in_sizes, int n_in,
                              void* d_out, int out_size) {
    const float* w = (const float*)d_in[0];   // [4,1]
    const float* x = (const float*)d_in[1];   // [1,4096]
    float* out = (float*)d_out;               // [4,4096,1] = 16384 floats

    const int total = B_DIM * T_DIM;          // 16384
    const int threads = 256;
    const int blocks = (total + threads - 1) / threads;  // 64
    tvp_kernel<<<blocks, threads>>>(w, x, out);
}

// round 2
// speedup vs baseline: 1.4789x; 1.4789x over previous
#include <cuda_runtime.h>

// Problem: B=4, T=4096, WINDOW=1024, MAX_DISP=2.0
// out[b,t] = linear interp of x at s = w[b]*coeff[t] + t (tent kernel collapses),
// out-of-range k dropped.
//
// Latency-bound kernel: the optimization here is overlapping the w load with a
// cooperative tile prefetch of x (address independent of w), so the two DRAM
// round trips run concurrently instead of serially.

#define T_DIM 4096
#define B_DIM 4
#define BLK   128      // threads per block; 128 blocks total, t-range per block = 128
#define HALO  64       // tile halo; |w*coeff| <= |w|, fallback path covers overflow
#define TILE  (BLK + 2 * HALO)   // 256 floats = 1 KB shared

__global__ void __launch_bounds__(BLK) tvp_kernel(const float* __restrict__ w,
                                                  const float* __restrict__ x,
                                                  float* __restrict__ out) {
    __shared__ float sx[TILE];

    const int tid = threadIdx.x;
    const int idx = blockIdx.x * BLK + tid;      // 0 .. B*T-1
    const int b   = idx >> 12;                   // 4096 t per b; BLK divides 4096
    const int t   = idx & (T_DIM - 1);
    const int t0  = t - tid;                     // block's first t
    const int base = t0 - HALO;                  // tile covers k in [base, base+TILE)

    // --- issue both independent loads up front ---
    // w broadcast (one 4B line, all lanes same address)
    float wb = __ldg(&w[b]);

    // cooperative x tile prefetch: 2 coalesced floats per thread, clamped addresses
    {
        int k_a = base + tid;
        int k_b = base + tid + BLK;
        int ca = min(max(k_a, 0), T_DIM - 1);
        int cb = min(max(k_b, 0), T_DIM - 1);
        float va = x[ca];                        // independent of wb -> overlaps
        float vb = x[cb];
        sx[tid]       = va;
        sx[tid + BLK] = vb;
    }
    __syncthreads();

    // --- dependent math (cheap) ---
    float wn = (float)(t & 1023);
    float c  = 2.0f * (wn * (1.0f / 1024.0f) - 0.5f);
    float s  = wb * c + (float)t;                // match reference mul-then-add

    float k0f  = floorf(s);
    int   k0   = (int)k0f;
    float frac = s - k0f;
    int   k1   = k0 + 1;

    int o0 = k0 - base;
    int o1 = o0 + 1;

    float acc = 0.0f;
    if (k0 >= 0 && k0 < T_DIM) {
        float v0 = (o0 >= 0 && o0 < TILE) ? sx[o0] : x[k0];  // fallback never taken in practice
        acc += (1.0f - frac) * v0;
    }
    if (k1 >= 0 && k1 < T_DIM) {
        float v1 = (o1 >= 0 && o1 < TILE) ? sx[o1] : x[k1];
        acc += frac * v1;
    }

    out[idx] = acc;
}

extern "C" void kernel_launch(void* const* d_in, const int* in_sizes, int n_in,
                              void* d_out, int out_size) {
    const float* w = (const float*)d_in[0];   // [4,1]
    const float* x = (const float*)d_in[1];   // [1,4096]
    float* out = (float*)d_out;               // [4,4096,1] = 16384 floats

    const int total  = B_DIM * T_DIM;         // 16384
    const int blocks = total / BLK;           // 128
    tvp_kernel<<<blocks, BLK>>>(w, x, out);
}